// round 5
// baseline (speedup 1.0000x reference)
#include <cuda_runtime.h>
#include <cstdint>

#define Bv 4
#define Nv 512
#define Dv 256
#define Lv 64

typedef unsigned long long ull;

// Scratch for projected features, transposed layout [b][l][n]  (512 KB)
__device__ float g_xh[Bv * Lv * Nv];

// ---------------------------------------------------------------------------
// Packed f32x2 helpers (sm_103a)
// ---------------------------------------------------------------------------
__device__ __forceinline__ ull pk2(float a) {
    ull r;
    asm("mov.b64 %0, {%1, %2};" : "=l"(r) : "f"(a), "f"(a));
    return r;
}
__device__ __forceinline__ ull add2(ull a, ull b) {
    ull r;
    asm("add.rn.f32x2 %0, %1, %2;" : "=l"(r) : "l"(a), "l"(b));
    return r;
}
__device__ __forceinline__ ull fma2(ull a, ull b, ull c) {
    ull r;
    asm("fma.rn.f32x2 %0, %1, %2, %3;" : "=l"(r) : "l"(a), "l"(b), "l"(c));
    return r;
}
__device__ __forceinline__ float lo2(ull a) {
    float x, y;
    asm("mov.b64 {%0, %1}, %2;" : "=f"(x), "=f"(y) : "l"(a));
    return x;
}
__device__ __forceinline__ float hi2(ull a) {
    float x, y;
    asm("mov.b64 {%0, %1}, %2;" : "=f"(x), "=f"(y) : "l"(a));
    return y;
}

// ---------------------------------------------------------------------------
// Kernel 1: x_hat[b,n,l] = sum_d x[b,n,d] * W[l,d], written as g_xh[b][l][n]
// ---------------------------------------------------------------------------
__global__ __launch_bounds__(256) void proj_kernel(const float* __restrict__ x,
                                                   const float* __restrict__ W) {
    extern __shared__ float sm[];
    float* xs = sm;                 // [256][17]
    float* Wt = sm + 256 * 17;      // [256][68]

    int b  = blockIdx.x >> 5;
    int n0 = (blockIdx.x & 31) << 4;
    int tid = threadIdx.x;

    for (int idx = tid; idx < 16 * 256; idx += 256) {
        int rr = idx >> 8, d = idx & 255;
        xs[d * 17 + rr] = x[(b * Nv + n0 + rr) * Dv + d];
    }
    for (int idx = tid; idx < 64 * 256; idx += 256) {
        int l = idx >> 8, d = idx & 255;
        Wt[d * 68 + l] = W[l * Dv + d];
    }
    __syncthreads();

    int r  = tid & 15;
    int l0 = (tid >> 4) << 2;

    float a0 = 0.f, a1 = 0.f, a2 = 0.f, a3 = 0.f;
#pragma unroll 8
    for (int d = 0; d < 256; ++d) {
        float  xv = xs[d * 17 + r];
        float4 wq = *(const float4*)&Wt[d * 68 + l0];
        a0 = fmaf(xv, wq.x, a0);
        a1 = fmaf(xv, wq.y, a1);
        a2 = fmaf(xv, wq.z, a2);
        a3 = fmaf(xv, wq.w, a3);
    }
    float* dst = g_xh + b * (Lv * Nv) + n0 + r;
    dst[(l0 + 0) * Nv] = a0;
    dst[(l0 + 1) * Nv] = a1;
    dst[(l0 + 2) * Nv] = a2;
    dst[(l0 + 3) * Nv] = a3;
}

// ---------------------------------------------------------------------------
// Kernel 2: fused dist + leaky_relu + row normalization.
// 1024 threads = 32 warps, grid 128 (b, 16-row i-tile).
// Warp w: rg=w&3 -> rows 4rg..4rg+3, jq=(w>>2)&3 -> j in [jq*128,+128),
//         lh=w>>4 -> l half. Lane: 4 j (one LDS.128) x 4 rows.
// j-vector is software-prefetched one l ahead (the only multi-phase LDS).
// ---------------------------------------------------------------------------
__global__ __launch_bounds__(1024, 1) void dist_softmax_kernel(
    const float* __restrict__ adj, const float* __restrict__ lw,
    float* __restrict__ out) {
    extern __shared__ float sm[];
    float* sj  = sm;                              // [64][512] x_hat[b]
    ull*   si2 = (ull*)(sm + Lv * Nv);            // [64][16]  {-v,-v}
    ull*   ws2 = si2 + 64 * 16;                   // [64]      {w,w}
    float* psum = (float*)(ws2 + 64);             // [16][512] lh partials
    float* red  = psum + 16 * 512;                // [2][16][4]

    int b  = blockIdx.x >> 5;
    int i0 = (blockIdx.x & 31) << 4;
    int tid = threadIdx.x;

    const float* xh = g_xh + b * (Lv * Nv);
    for (int idx = tid; idx < (Lv * Nv) / 4; idx += 1024)
        ((float4*)sj)[idx] = ((const float4*)xh)[idx];
    {
        int l = tid >> 4, row = tid & 15;          // 1024 = 64*16 exactly
        si2[l * 16 + row] = pk2(-xh[l * Nv + i0 + row]);
    }
    if (tid < 64) ws2[tid] = pk2(lw[tid]);
    __syncthreads();

    int w    = tid >> 5;
    int lane = tid & 31;
    int rg = w & 3;
    int jq = (w >> 2) & 3;
    int lh = w >> 4;
    int jbase = jq * 128 + lane * 4;
    int lb = lh * 32;

    const ull ABS2 = 0x7FFFFFFF7FFFFFFFull;
    ull a00 = 0, a01 = 0, a10 = 0, a11 = 0;
    ull a20 = 0, a21 = 0, a30 = 0, a31 = 0;

    const float* sjp = sj + (size_t)lb * Nv + jbase;
    const ull*   sip = si2 + lb * 16 + rg * 4;
    const ull*   wsp = ws2 + lb;

    // prefetch l=0 j-vector
    ulonglong2 jn = *(const ulonglong2*)sjp;
#pragma unroll 8
    for (int l = 0; l < 32; ++l) {
        ulonglong2 j01 = jn;
        // prefetch next iteration's j (wrap-around on last iter: harmless)
        jn = *(const ulonglong2*)(sjp + (size_t)((l + 1) & 31) * Nv);
        ull        w2  = wsp[l];
        ulonglong2 nab = *(const ulonglong2*)(sip + l * 16);
        ulonglong2 ncd = *(const ulonglong2*)(sip + l * 16 + 2);
        a00 = fma2(w2, add2(j01.x, nab.x) & ABS2, a00);
        a01 = fma2(w2, add2(j01.y, nab.x) & ABS2, a01);
        a10 = fma2(w2, add2(j01.x, nab.y) & ABS2, a10);
        a11 = fma2(w2, add2(j01.y, nab.y) & ABS2, a11);
        a20 = fma2(w2, add2(j01.x, ncd.x) & ABS2, a20);
        a21 = fma2(w2, add2(j01.y, ncd.x) & ABS2, a21);
        a30 = fma2(w2, add2(j01.x, ncd.y) & ABS2, a30);
        a31 = fma2(w2, add2(j01.y, ncd.y) & ABS2, a31);
    }

    // d[r][k]: row (4rg+r), column (jbase+k)
    float d[4][4];
    d[0][0] = lo2(a00); d[0][1] = hi2(a00); d[0][2] = lo2(a01); d[0][3] = hi2(a01);
    d[1][0] = lo2(a10); d[1][1] = hi2(a10); d[1][2] = lo2(a11); d[1][3] = hi2(a11);
    d[2][0] = lo2(a20); d[2][1] = hi2(a20); d[2][2] = lo2(a21); d[2][3] = hi2(a21);
    d[3][0] = lo2(a30); d[3][1] = hi2(a30); d[3][2] = lo2(a31); d[3][3] = hi2(a31);

    if (lh == 0) {
#pragma unroll
        for (int r = 0; r < 4; ++r) {
            float4 p4 = make_float4(d[r][0], d[r][1], d[r][2], d[r][3]);
            *(float4*)&psum[(rg * 4 + r) * Nv + jbase] = p4;
        }
    }
    __syncthreads();

    float m[4];
    if (lh == 1) {
#pragma unroll
        for (int r = 0; r < 4; ++r) {
            float4 p4 = *(const float4*)&psum[(rg * 4 + r) * Nv + jbase];
            d[r][0] += p4.x; d[r][1] += p4.y; d[r][2] += p4.z; d[r][3] += p4.w;
            float mr = -1e30f;
#pragma unroll
            for (int k = 0; k < 4; ++k) {
                float v = d[r][k];
                v = v > 0.f ? v : 0.01f * v;
                d[r][k] = v;
                mr = fmaxf(mr, v);
            }
#pragma unroll
            for (int o = 16; o; o >>= 1)
                mr = fmaxf(mr, __shfl_xor_sync(0xffffffffu, mr, o));
            m[r] = mr;
        }
        if (lane == 0) {
#pragma unroll
            for (int r = 0; r < 4; ++r)
                red[(rg * 4 + r) * 4 + jq] = m[r];
        }
    }
    __syncthreads();

    float s[4];
    if (lh == 1) {
#pragma unroll
        for (int r = 0; r < 4; ++r) {
            int row = rg * 4 + r;
            float M = fmaxf(fmaxf(red[row * 4 + 0], red[row * 4 + 1]),
                            fmaxf(red[row * 4 + 2], red[row * 4 + 3]));
            const float* arow = adj + (size_t)(b * Nv + i0 + row) * Nv;
            float4 av = *(const float4*)&arow[jbase];
            float sr = 0.f, v;
            v = av.x * __expf(d[r][0] - M); d[r][0] = v; sr += v;
            v = av.y * __expf(d[r][1] - M); d[r][1] = v; sr += v;
            v = av.z * __expf(d[r][2] - M); d[r][2] = v; sr += v;
            v = av.w * __expf(d[r][3] - M); d[r][3] = v; sr += v;
#pragma unroll
            for (int o = 16; o; o >>= 1)
                sr += __shfl_xor_sync(0xffffffffu, sr, o);
            s[r] = sr;
        }
        if (lane == 0) {
#pragma unroll
            for (int r = 0; r < 4; ++r)
                red[64 + (rg * 4 + r) * 4 + jq] = s[r];
        }
    }
    __syncthreads();

    if (lh == 1) {
#pragma unroll
        for (int r = 0; r < 4; ++r) {
            int row = rg * 4 + r;
            float S = red[64 + row * 4 + 0] + red[64 + row * 4 + 1] +
                      red[64 + row * 4 + 2] + red[64 + row * 4 + 3];
            float rs = 1.0f / S;
            float4 o4;
            o4.x = d[r][0] * rs + 1e-10f;
            o4.y = d[r][1] * rs + 1e-10f;
            o4.z = d[r][2] * rs + 1e-10f;
            o4.w = d[r][3] * rs + 1e-10f;
            *(float4*)&out[(size_t)(b * Nv + i0 + row) * Nv + jbase] = o4;
        }
    }
}

extern "C" void kernel_launch(void* const* d_in, const int* in_sizes, int n_in,
                              void* d_out, int out_size) {
    (void)in_sizes; (void)n_in; (void)out_size;
    const float* x   = (const float*)d_in[0];
    const float* adj = (const float*)d_in[1];
    const float* W   = (const float*)d_in[2];
    const float* lw  = (const float*)d_in[3];
    float* out = (float*)d_out;

    const int smem1 = (256 * 17 + 256 * 68) * 4;
    const int smem2 = (32768 + 2048 + 128 + 8192 + 128) * 4;   // 173056 B

    cudaFuncSetAttribute(proj_kernel,
                         cudaFuncAttributeMaxDynamicSharedMemorySize, smem1);
    cudaFuncSetAttribute(dist_softmax_kernel,
                         cudaFuncAttributeMaxDynamicSharedMemorySize, smem2);
    // Pin BOTH kernels to the same shared-memory carveout so the driver does
    // not reconfigure the SM L1/smem split between the two launches (and
    // between graph-replay iterations).
    cudaFuncSetAttribute(proj_kernel,
                         cudaFuncAttributePreferredSharedMemoryCarveout,
                         cudaSharedmemCarveoutMaxShared);
    cudaFuncSetAttribute(dist_softmax_kernel,
                         cudaFuncAttributePreferredSharedMemoryCarveout,
                         cudaSharedmemCarveoutMaxShared);

    proj_kernel<<<Bv * (Nv / 16), 256, smem1>>>(x, W);
    dist_softmax_kernel<<<Bv * (Nv / 16), 1024, smem2>>>(adj, lw, out);
}

// round 6
// speedup vs baseline: 1.0945x; 1.0945x over previous
#include <cuda_runtime.h>
#include <cstdint>

#define Bv 4
#define Nv 512
#define Dv 256
#define Lv 64

typedef unsigned long long ull;

// Scratch for projected features, transposed layout [b][l][n]  (512 KB)
__device__ float g_xh[Bv * Lv * Nv];
// Device-wide barrier state (replay-safe: count resets, release monotone)
__device__ unsigned g_count = 0;
__device__ unsigned g_release = 0;

// ---------------------------------------------------------------------------
// Packed f32x2 helpers (sm_103a)
// ---------------------------------------------------------------------------
__device__ __forceinline__ ull pk2(float a) {
    ull r;
    asm("mov.b64 %0, {%1, %2};" : "=l"(r) : "f"(a), "f"(a));
    return r;
}
__device__ __forceinline__ ull add2(ull a, ull b) {
    ull r;
    asm("add.rn.f32x2 %0, %1, %2;" : "=l"(r) : "l"(a), "l"(b));
    return r;
}
__device__ __forceinline__ ull fma2(ull a, ull b, ull c) {
    ull r;
    asm("fma.rn.f32x2 %0, %1, %2, %3;" : "=l"(r) : "l"(a), "l"(b), "l"(c));
    return r;
}
__device__ __forceinline__ float lo2(ull a) {
    float x, y;
    asm("mov.b64 {%0, %1}, %2;" : "=f"(x), "=f"(y) : "l"(a));
    return x;
}
__device__ __forceinline__ float hi2(ull a) {
    float x, y;
    asm("mov.b64 {%0, %1}, %2;" : "=f"(x), "=f"(y) : "l"(a));
    return y;
}

// ---------------------------------------------------------------------------
// Fused kernel: projection -> device barrier -> dist + leaky_relu + softmax
// Grid 128 = (b, 16-row i-tile), 1024 threads, 173 KB smem (1 CTA/SM,
// single wave -> spin barrier is safe).
// ---------------------------------------------------------------------------
__global__ __launch_bounds__(1024, 1) void fused_kernel(
    const float* __restrict__ x, const float* __restrict__ adj,
    const float* __restrict__ W, const float* __restrict__ lw,
    float* __restrict__ out) {
    extern __shared__ float sm[];
    // Phase-B layout
    float* sj   = sm;                              // [64][512] x_hat[b]
    ull*   si2  = (ull*)(sm + Lv * Nv);            // [64][16]  {-v,-v}
    ull*   ws2  = si2 + 64 * 16;                   // [64]      {w,w}
    float* psum = (float*)(ws2 + 64);              // [16][512] lh partials
    float* red  = psum + 16 * 512;                 // [2][16][4]
    // Phase-A aliases (dead regions during phase A)
    float* Wt = sm;                                // [256][68] in sj area
    float* xs = psum;                              // [256][17] in psum area

    int b  = blockIdx.x >> 5;
    int i0 = (blockIdx.x & 31) << 4;
    int tid = threadIdx.x;

    // ---------------- Phase A: projection of this block's 16 i-rows --------
    for (int idx = tid; idx < 16 * 256; idx += 1024) {
        int rr = idx >> 8, d = idx & 255;
        xs[d * 17 + rr] = x[(b * Nv + i0 + rr) * Dv + d];
    }
    for (int idx = tid; idx < 64 * 256; idx += 1024) {
        int l = idx >> 8, d = idx & 255;
        Wt[d * 68 + l] = W[l * Dv + d];
    }
    if (tid < 64) ws2[tid] = pk2(lw[tid]);
    __syncthreads();

    if (tid < 256) {
        int r  = tid & 15;
        int l0 = (tid >> 4) << 2;
        float a0 = 0.f, a1 = 0.f, a2 = 0.f, a3 = 0.f;
#pragma unroll 8
        for (int d = 0; d < 256; ++d) {
            float  xv = xs[d * 17 + r];
            float4 wq = *(const float4*)&Wt[d * 68 + l0];
            a0 = fmaf(xv, wq.x, a0);
            a1 = fmaf(xv, wq.y, a1);
            a2 = fmaf(xv, wq.z, a2);
            a3 = fmaf(xv, wq.w, a3);
        }
        float* dst = g_xh + b * (Lv * Nv) + i0 + r;
        dst[(l0 + 0) * Nv] = a0;
        dst[(l0 + 1) * Nv] = a1;
        dst[(l0 + 2) * Nv] = a2;
        dst[(l0 + 3) * Nv] = a3;
        // own i-rows, packed & negated, straight into si2
        si2[(l0 + 0) * 16 + r] = pk2(-a0);
        si2[(l0 + 1) * 16 + r] = pk2(-a1);
        si2[(l0 + 2) * 16 + r] = pk2(-a2);
        si2[(l0 + 3) * 16 + r] = pk2(-a3);
    }
    __syncthreads();

    // ---------------- Device-wide barrier ----------------------------------
    if (tid == 0) {
        __threadfence();
        unsigned snap = *(volatile unsigned*)&g_release;   // BEFORE arriving
        unsigned old  = atomicAdd(&g_count, 1);
        if (old == gridDim.x - 1) {
            g_count = 0;
            __threadfence();
            atomicAdd(&g_release, 1);
        } else {
            while (*(volatile unsigned*)&g_release == snap) __nanosleep(64);
        }
        __threadfence();
    }
    __syncthreads();

    // ---------------- Phase B: stage sj, mainloop, epilogue ----------------
    const float* xh = g_xh + b * (Lv * Nv);
    for (int idx = tid; idx < (Lv * Nv) / 4; idx += 1024)
        ((float4*)sj)[idx] = ((const float4*)xh)[idx];
    __syncthreads();

    int w    = tid >> 5;
    int lane = tid & 31;
    int rg = w & 3;
    int jq = (w >> 2) & 3;
    int lh = w >> 4;
    int jbase = jq * 128 + lane * 4;
    int lb = lh * 32;

    const ull ABS2 = 0x7FFFFFFF7FFFFFFFull;
    ull a00 = 0, a01 = 0, a10 = 0, a11 = 0;
    ull a20 = 0, a21 = 0, a30 = 0, a31 = 0;

    const float* sjp = sj + (size_t)lb * Nv + jbase;
    const ull*   sip = si2 + lb * 16 + rg * 4;
    const ull*   wsp = ws2 + lb;

    ulonglong2 jn = *(const ulonglong2*)sjp;
#pragma unroll 8
    for (int l = 0; l < 32; ++l) {
        ulonglong2 j01 = jn;
        jn = *(const ulonglong2*)(sjp + (size_t)((l + 1) & 31) * Nv);
        ull        w2  = wsp[l];
        ulonglong2 nab = *(const ulonglong2*)(sip + l * 16);
        ulonglong2 ncd = *(const ulonglong2*)(sip + l * 16 + 2);
        a00 = fma2(w2, add2(j01.x, nab.x) & ABS2, a00);
        a01 = fma2(w2, add2(j01.y, nab.x) & ABS2, a01);
        a10 = fma2(w2, add2(j01.x, nab.y) & ABS2, a10);
        a11 = fma2(w2, add2(j01.y, nab.y) & ABS2, a11);
        a20 = fma2(w2, add2(j01.x, ncd.x) & ABS2, a20);
        a21 = fma2(w2, add2(j01.y, ncd.x) & ABS2, a21);
        a30 = fma2(w2, add2(j01.x, ncd.y) & ABS2, a30);
        a31 = fma2(w2, add2(j01.y, ncd.y) & ABS2, a31);
    }

    float d[4][4];
    d[0][0] = lo2(a00); d[0][1] = hi2(a00); d[0][2] = lo2(a01); d[0][3] = hi2(a01);
    d[1][0] = lo2(a10); d[1][1] = hi2(a10); d[1][2] = lo2(a11); d[1][3] = hi2(a11);
    d[2][0] = lo2(a20); d[2][1] = hi2(a20); d[2][2] = lo2(a21); d[2][3] = hi2(a21);
    d[3][0] = lo2(a30); d[3][1] = hi2(a30); d[3][2] = lo2(a31); d[3][3] = hi2(a31);

    if (lh == 0) {
#pragma unroll
        for (int r = 0; r < 4; ++r) {
            float4 p4 = make_float4(d[r][0], d[r][1], d[r][2], d[r][3]);
            *(float4*)&psum[(rg * 4 + r) * Nv + jbase] = p4;
        }
    }
    __syncthreads();

    float m[4];
    if (lh == 1) {
#pragma unroll
        for (int r = 0; r < 4; ++r) {
            float4 p4 = *(const float4*)&psum[(rg * 4 + r) * Nv + jbase];
            d[r][0] += p4.x; d[r][1] += p4.y; d[r][2] += p4.z; d[r][3] += p4.w;
            float mr = -1e30f;
#pragma unroll
            for (int k = 0; k < 4; ++k) {
                float v = d[r][k];
                v = v > 0.f ? v : 0.01f * v;
                d[r][k] = v;
                mr = fmaxf(mr, v);
            }
#pragma unroll
            for (int o = 16; o; o >>= 1)
                mr = fmaxf(mr, __shfl_xor_sync(0xffffffffu, mr, o));
            m[r] = mr;
        }
        if (lane == 0) {
#pragma unroll
            for (int r = 0; r < 4; ++r)
                red[(rg * 4 + r) * 4 + jq] = m[r];
        }
    }
    __syncthreads();

    float s[4];
    if (lh == 1) {
#pragma unroll
        for (int r = 0; r < 4; ++r) {
            int row = rg * 4 + r;
            float M = fmaxf(fmaxf(red[row * 4 + 0], red[row * 4 + 1]),
                            fmaxf(red[row * 4 + 2], red[row * 4 + 3]));
            const float* arow = adj + (size_t)(b * Nv + i0 + row) * Nv;
            float4 av = *(const float4*)&arow[jbase];
            float sr = 0.f, v;
            v = av.x * __expf(d[r][0] - M); d[r][0] = v; sr += v;
            v = av.y * __expf(d[r][1] - M); d[r][1] = v; sr += v;
            v = av.z * __expf(d[r][2] - M); d[r][2] = v; sr += v;
            v = av.w * __expf(d[r][3] - M); d[r][3] = v; sr += v;
#pragma unroll
            for (int o = 16; o; o >>= 1)
                sr += __shfl_xor_sync(0xffffffffu, sr, o);
            s[r] = sr;
        }
        if (lane == 0) {
#pragma unroll
            for (int r = 0; r < 4; ++r)
                red[64 + (rg * 4 + r) * 4 + jq] = s[r];
        }
    }
    __syncthreads();

    if (lh == 1) {
#pragma unroll
        for (int r = 0; r < 4; ++r) {
            int row = rg * 4 + r;
            float S = red[64 + row * 4 + 0] + red[64 + row * 4 + 1] +
                      red[64 + row * 4 + 2] + red[64 + row * 4 + 3];
            float rs = 1.0f / S;
            float4 o4;
            o4.x = d[r][0] * rs + 1e-10f;
            o4.y = d[r][1] * rs + 1e-10f;
            o4.z = d[r][2] * rs + 1e-10f;
            o4.w = d[r][3] * rs + 1e-10f;
            *(float4*)&out[(size_t)(b * Nv + i0 + row) * Nv + jbase] = o4;
        }
    }
}

extern "C" void kernel_launch(void* const* d_in, const int* in_sizes, int n_in,
                              void* d_out, int out_size) {
    (void)in_sizes; (void)n_in; (void)out_size;
    const float* x   = (const float*)d_in[0];
    const float* adj = (const float*)d_in[1];
    const float* W   = (const float*)d_in[2];
    const float* lw  = (const float*)d_in[3];
    float* out = (float*)d_out;

    const int smem = (32768 + 2048 + 128 + 8192 + 128) * 4;   // 173056 B
    cudaFuncSetAttribute(fused_kernel,
                         cudaFuncAttributeMaxDynamicSharedMemorySize, smem);
    cudaFuncSetAttribute(fused_kernel,
                         cudaFuncAttributePreferredSharedMemoryCarveout,
                         cudaSharedmemCarveoutMaxShared);

    fused_kernel<<<Bv * (Nv / 16), 1024, smem>>>(x, adj, W, lw, out);
}

// round 7
// speedup vs baseline: 1.1015x; 1.0064x over previous
#include <cuda_runtime.h>
#include <cstdint>

#define Bv 4
#define Nv 512
#define Dv 256
#define Lv 64

typedef unsigned long long ull;

// Scratch for projected+weighted features, layout [b][l][n]  (512 KB)
__device__ float g_xh[Bv * Lv * Nv];
// Device-wide barrier state (replay-safe: count resets, release monotone)
__device__ unsigned g_count = 0;
__device__ unsigned g_release = 0;

// ---------------------------------------------------------------------------
// Packed f32x2 helpers (sm_103a)
// ---------------------------------------------------------------------------
__device__ __forceinline__ ull pk2(float a) {
    ull r;
    asm("mov.b64 %0, {%1, %2};" : "=l"(r) : "f"(a), "f"(a));
    return r;
}
__device__ __forceinline__ ull add2(ull a, ull b) {
    ull r;
    asm("add.rn.f32x2 %0, %1, %2;" : "=l"(r) : "l"(a), "l"(b));
    return r;
}
__device__ __forceinline__ float lo2(ull a) {
    float x, y;
    asm("mov.b64 {%0, %1}, %2;" : "=f"(x), "=f"(y) : "l"(a));
    return x;
}
__device__ __forceinline__ float hi2(ull a) {
    float x, y;
    asm("mov.b64 {%0, %1}, %2;" : "=f"(x), "=f"(y) : "l"(a));
    return y;
}

// ---------------------------------------------------------------------------
// Fused kernel: weighted projection -> device barrier -> dist + epilogue.
// Grid 128 = (b, 16-row i-tile), 1024 threads, ~173 KB smem (1 CTA/SM,
// single wave -> spin barrier safe).
// Weights folded: g_xh holds w_l * (x @ W^T)[l][n]; since learn_w >= 0,
// sum_l w|xi-xj| == sum_l |w*xi - w*xj|.
// ---------------------------------------------------------------------------
__global__ __launch_bounds__(1024, 1) void fused_kernel(
    const float* __restrict__ x, const float* __restrict__ adj,
    const float* __restrict__ W, const float* __restrict__ lw,
    float* __restrict__ out) {
    extern __shared__ float sm[];
    // Phase-B layout
    float* sj   = sm;                              // [64][512] w*x_hat[b]
    ull*   si2  = (ull*)(sm + Lv * Nv);            // [64][16]  {-wv,-wv}
    float* psum = (float*)(si2 + 64 * 16);         // [16][512] lh partials
    float* red  = psum + 16 * 512;                 // [2][16][4]
    // Phase-A aliases (dead regions during phase A)
    float* Wt = sm;                                // [256][68] in sj area
    float* xs = psum;                              // [256][17] in psum area

    int b  = blockIdx.x >> 5;
    int i0 = (blockIdx.x & 31) << 4;
    int tid = threadIdx.x;

    // ---------------- Phase A: weighted projection of this block's 16 rows -
    for (int idx = tid; idx < 16 * 256; idx += 1024) {
        int rr = idx >> 8, d = idx & 255;
        xs[d * 17 + rr] = x[(b * Nv + i0 + rr) * Dv + d];
    }
    for (int idx = tid; idx < 64 * 256; idx += 1024) {
        int l = idx >> 8, d = idx & 255;
        Wt[d * 68 + l] = W[l * Dv + d];
    }
    __syncthreads();

    if (tid < 256) {
        int r  = tid & 15;
        int l0 = (tid >> 4) << 2;
        float a0 = 0.f, a1 = 0.f, a2 = 0.f, a3 = 0.f;
#pragma unroll 8
        for (int d = 0; d < 256; ++d) {
            float  xv = xs[d * 17 + r];
            float4 wq = *(const float4*)&Wt[d * 68 + l0];
            a0 = fmaf(xv, wq.x, a0);
            a1 = fmaf(xv, wq.y, a1);
            a2 = fmaf(xv, wq.z, a2);
            a3 = fmaf(xv, wq.w, a3);
        }
        // fold learn_w (>= 0) here
        a0 *= lw[l0 + 0];
        a1 *= lw[l0 + 1];
        a2 *= lw[l0 + 2];
        a3 *= lw[l0 + 3];
        float* dst = g_xh + b * (Lv * Nv) + i0 + r;
        dst[(l0 + 0) * Nv] = a0;
        dst[(l0 + 1) * Nv] = a1;
        dst[(l0 + 2) * Nv] = a2;
        dst[(l0 + 3) * Nv] = a3;
        si2[(l0 + 0) * 16 + r] = pk2(-a0);
        si2[(l0 + 1) * 16 + r] = pk2(-a1);
        si2[(l0 + 2) * 16 + r] = pk2(-a2);
        si2[(l0 + 3) * 16 + r] = pk2(-a3);
    }
    __syncthreads();

    // ---------------- Device-wide barrier ----------------------------------
    if (tid == 0) {
        __threadfence();
        unsigned snap = *(volatile unsigned*)&g_release;   // BEFORE arriving
        unsigned old  = atomicAdd(&g_count, 1);
        if (old == gridDim.x - 1) {
            g_count = 0;
            __threadfence();
            atomicAdd(&g_release, 1);
        } else {
            while (*(volatile unsigned*)&g_release == snap) __nanosleep(64);
        }
        __threadfence();
    }
    __syncthreads();

    // ---------------- Phase B: stage sj, mainloop, epilogue ----------------
    const float* xh = g_xh + b * (Lv * Nv);
    for (int idx = tid; idx < (Lv * Nv) / 4; idx += 1024)
        ((float4*)sj)[idx] = ((const float4*)xh)[idx];
    __syncthreads();

    int w    = tid >> 5;
    int lane = tid & 31;
    int rg = w & 3;
    int jq = (w >> 2) & 3;
    int lh = w >> 4;
    int jbase = jq * 128 + lane * 4;
    int lb = lh * 32;

    const ull ABS2 = 0x7FFFFFFF7FFFFFFFull;
    ull a00 = 0, a01 = 0, a10 = 0, a11 = 0;
    ull a20 = 0, a21 = 0, a30 = 0, a31 = 0;

    const float* sjp = sj + (size_t)lb * Nv + jbase;
    const ull*   sip = si2 + lb * 16 + rg * 4;

#pragma unroll
    for (int l = 0; l < 32; ++l) {
        ulonglong2 j01 = *(const ulonglong2*)(sjp + (size_t)l * Nv);
        ulonglong2 nab = *(const ulonglong2*)(sip + l * 16);
        ulonglong2 ncd = *(const ulonglong2*)(sip + l * 16 + 2);
        a00 = add2(a00, add2(j01.x, nab.x) & ABS2);
        a01 = add2(a01, add2(j01.y, nab.x) & ABS2);
        a10 = add2(a10, add2(j01.x, nab.y) & ABS2);
        a11 = add2(a11, add2(j01.y, nab.y) & ABS2);
        a20 = add2(a20, add2(j01.x, ncd.x) & ABS2);
        a21 = add2(a21, add2(j01.y, ncd.x) & ABS2);
        a30 = add2(a30, add2(j01.x, ncd.y) & ABS2);
        a31 = add2(a31, add2(j01.y, ncd.y) & ABS2);
    }

    // d[r][k]: row (4rg+r), column (jbase+k)
    float d[4][4];
    d[0][0] = lo2(a00); d[0][1] = hi2(a00); d[0][2] = lo2(a01); d[0][3] = hi2(a01);
    d[1][0] = lo2(a10); d[1][1] = hi2(a10); d[1][2] = lo2(a11); d[1][3] = hi2(a11);
    d[2][0] = lo2(a20); d[2][1] = hi2(a20); d[2][2] = lo2(a21); d[2][3] = hi2(a21);
    d[3][0] = lo2(a30); d[3][1] = hi2(a30); d[3][2] = lo2(a31); d[3][3] = hi2(a31);

    if (lh == 0) {
#pragma unroll
        for (int r = 0; r < 4; ++r) {
            float4 p4 = make_float4(d[r][0], d[r][1], d[r][2], d[r][3]);
            *(float4*)&psum[(rg * 4 + r) * Nv + jbase] = p4;
        }
    }
    __syncthreads();

    float m[4];
    if (lh == 1) {
#pragma unroll
        for (int r = 0; r < 4; ++r) {
            float4 p4 = *(const float4*)&psum[(rg * 4 + r) * Nv + jbase];
            d[r][0] += p4.x; d[r][1] += p4.y; d[r][2] += p4.z; d[r][3] += p4.w;
            float mr = -1e30f;
#pragma unroll
            for (int k = 0; k < 4; ++k) {
                float v = d[r][k];
                v = v > 0.f ? v : 0.01f * v;
                d[r][k] = v;
                mr = fmaxf(mr, v);
            }
#pragma unroll
            for (int o = 16; o; o >>= 1)
                mr = fmaxf(mr, __shfl_xor_sync(0xffffffffu, mr, o));
            m[r] = mr;
        }
        if (lane == 0) {
#pragma unroll
            for (int r = 0; r < 4; ++r)
                red[(rg * 4 + r) * 4 + jq] = m[r];
        }
    }
    __syncthreads();

    float s[4];
    if (lh == 1) {
#pragma unroll
        for (int r = 0; r < 4; ++r) {
            int row = rg * 4 + r;
            float M = fmaxf(fmaxf(red[row * 4 + 0], red[row * 4 + 1]),
                            fmaxf(red[row * 4 + 2], red[row * 4 + 3]));
            const float* arow = adj + (size_t)(b * Nv + i0 + row) * Nv;
            float4 av = *(const float4*)&arow[jbase];
            float sr = 0.f, v;
            v = av.x * __expf(d[r][0] - M); d[r][0] = v; sr += v;
            v = av.y * __expf(d[r][1] - M); d[r][1] = v; sr += v;
            v = av.z * __expf(d[r][2] - M); d[r][2] = v; sr += v;
            v = av.w * __expf(d[r][3] - M); d[r][3] = v; sr += v;
#pragma unroll
            for (int o = 16; o; o >>= 1)
                sr += __shfl_xor_sync(0xffffffffu, sr, o);
            s[r] = sr;
        }
        if (lane == 0) {
#pragma unroll
            for (int r = 0; r < 4; ++r)
                red[64 + (rg * 4 + r) * 4 + jq] = s[r];
        }
    }
    __syncthreads();

    if (lh == 1) {
#pragma unroll
        for (int r = 0; r < 4; ++r) {
            int row = rg * 4 + r;
            float S = red[64 + row * 4 + 0] + red[64 + row * 4 + 1] +
                      red[64 + row * 4 + 2] + red[64 + row * 4 + 3];
            float rs = 1.0f / S;
            float4 o4;
            o4.x = d[r][0] * rs + 1e-10f;
            o4.y = d[r][1] * rs + 1e-10f;
            o4.z = d[r][2] * rs + 1e-10f;
            o4.w = d[r][3] * rs + 1e-10f;
            *(float4*)&out[(size_t)(b * Nv + i0 + row) * Nv + jbase] = o4;
        }
    }
}

extern "C" void kernel_launch(void* const* d_in, const int* in_sizes, int n_in,
                              void* d_out, int out_size) {
    (void)in_sizes; (void)n_in; (void)out_size;
    const float* x   = (const float*)d_in[0];
    const float* adj = (const float*)d_in[1];
    const float* W   = (const float*)d_in[2];
    const float* lw  = (const float*)d_in[3];
    float* out = (float*)d_out;

    // sj 131072 + si2 8192 + psum 32768 + red 512 bytes
    const int smem = 131072 + 8192 + 32768 + 512;   // 172544 B
    cudaFuncSetAttribute(fused_kernel,
                         cudaFuncAttributeMaxDynamicSharedMemorySize, smem);
    cudaFuncSetAttribute(fused_kernel,
                         cudaFuncAttributePreferredSharedMemoryCarveout,
                         cudaSharedmemCarveoutMaxShared);

    fused_kernel<<<Bv * (Nv / 16), 1024, smem>>>(x, adj, W, lw, out);
}